// round 11
// baseline (speedup 1.0000x reference)
#include <cuda_runtime.h>
#include <cuda_bf16.h>
#include <cstdint>

// ============================================================================
// NeRF fused MLP on tcgen05 (bf16 2-term split, fp32 TMEM accumulate).
// R11: 4-buffer / prefetch-distance-3 async weight pipeline, 16KB SW64 chunks.
//
// Scratch: 140 consecutive 16KB chunk frames (one per K16 step of every
// layer). Frame = 256 N-rows x 64B, SW64 swizzle: bf16 hi at frame K-cols
// [0,16), lo at [16,32). Copy = one cp.async.bulk of 16KB.
// Control thread (tid 0), per global chunk g:
//   wait full[g%4] -> 3 MMAs (hh, h*Blo, Alo*Bh) -> commit mma[g%4]
//   -> free-wait mma[g-1] (paces loop; pipe still holds chunk g)
//   -> bulk-copy chunk g+3 into freed buffer (flat cross-layer schedule).
// Layer completion via a dedicated commit barrier (keeps per-buffer
// parities 1:1). Epilogue: LDTM f32 + bias + ReLU, re-split bf16 hi/lo to
// the SW128 A tiles. Copies prefetched 3 ahead cover the epilogue gap.
//
// tcgen05 asm guarded by HAS_TC (generic compute_103 PTX variant must not
// contain it; never executed). cp.async.bulk/mbarrier are sm_90 baseline.
// ============================================================================

#if defined(__CUDA_ARCH_FEAT_SM103_ALL) || defined(__CUDA_ARCH_FEAT_SM100_ALL) || defined(__CUDA_ARCH_FEAT_SM101_ALL)
#define HAS_TC 1
#else
#define HAS_TC 0
#endif

#define TPB        512
#define MROWS      128
#define AHI_OFF    0
#define ALO_OFF    81920
#define B_OFF      163840            // 4 x 16KB buffers
#define TMEMP_OFF  229376
#define MBAR_OFF   229384            // full[4]@+0..31, mma[4]@+32..63, layer@+64
#define SMEM_BYTES 229456
#define D1         0
#define D2         256
#define CH_BYTES   16384u
#define NCH_TOTAL  140
// idesc kind::f16: dtype=F32(1<<4), a=BF16(1<<7), b=BF16(1<<10), N=256, M=128
#define IDESC      0x8400490u
#define WSCRATCH_BYTES (NCH_TOTAL * CH_BYTES)

__device__ __align__(128) unsigned char g_wscratch[WSCRATCH_BYTES];

static __device__ __forceinline__ uint32_t swz128(uint32_t b) { return b ^ ((b >> 3) & 0x70); }
static __device__ __forceinline__ uint32_t swz64(uint32_t b)  { return b ^ ((b >> 3) & 0x30); }
// A tile (SW128 blocked atoms, 128 rows x 320 K-cols)
static __device__ __forceinline__ uint32_t tile_off(int r, int k) {
    return (uint32_t)(((k >> 6) * 16 + (r >> 3)) * 1024)
         + swz128((uint32_t)(((r & 7) << 7) | ((k & 63) << 1)));
}
// B chunk frame (SW64, 256 rows x 32 cols bf16 = 64B rows)
static __device__ __forceinline__ uint32_t b_off64(int n, int c) {
    return (uint32_t)((n >> 3) * 512)
         + swz64((uint32_t)(((n & 7) << 6) | (c << 1)));
}
static __device__ __forceinline__ uint32_t smem_u32(const void* p) {
    uint32_t a;
    asm("{ .reg .u64 t; cvta.to.shared.u64 t, %1; cvt.u32.u64 %0, t; }" : "=r"(a) : "l"(p));
    return a;
}
static __device__ __forceinline__ uint64_t mkdesc128(uint32_t addr) {
    const uint64_t base = (uint64_t(2) << 61) | (uint64_t(1) << 46)
                        | (uint64_t(64) << 32) | (uint64_t(1) << 16);
    return base | ((uint64_t)(addr >> 4) & 0x3FFF);
}
static __device__ __forceinline__ uint64_t mkdesc64(uint32_t addr) {
    const uint64_t base = (uint64_t(4) << 61) | (uint64_t(1) << 46)
                        | (uint64_t(32) << 32) | (uint64_t(1) << 16);
    return base | ((uint64_t)(addr >> 4) & 0x3FFF);
}

static __device__ __forceinline__ void mma_ss(uint32_t d, uint64_t ad, uint64_t bd, uint32_t en) {
#if HAS_TC
    asm volatile(
        "{ .reg .pred p; setp.ne.u32 p, %5, 0;\n\t"
        "tcgen05.mma.cta_group::1.kind::f16 [%0], %1, %2, %3, {%4,%4,%4,%4}, p; }"
        :: "r"(d), "l"(ad), "l"(bd), "r"(IDESC), "r"(0u), "r"(en) : "memory");
#endif
}
static __device__ __forceinline__ void mbar_init(uint32_t a, uint32_t cnt) {
    asm volatile("mbarrier.init.shared.b64 [%0], %1;" :: "r"(a), "r"(cnt) : "memory");
}
static __device__ __forceinline__ void mbar_expect_tx(uint32_t a, uint32_t bytes) {
    asm volatile("mbarrier.arrive.expect_tx.shared.b64 _, [%0], %1;" :: "r"(a), "r"(bytes) : "memory");
}
static __device__ __forceinline__ void bulk_copy16k(uint32_t dst, const void* src, uint32_t mbar) {
    asm volatile(
        "cp.async.bulk.shared::cluster.global.mbarrier::complete_tx::bytes [%0], [%1], %2, [%3];"
        :: "r"(dst), "l"(src), "r"(CH_BYTES), "r"(mbar) : "memory");
}
static __device__ __forceinline__ void mbar_wait(uint32_t a, uint32_t parity) {
    uint32_t done;
    asm volatile(
        "{ .reg .pred p; mbarrier.try_wait.parity.acquire.cta.shared::cta.b64 p, [%1], %2;"
        " selp.b32 %0, 1, 0, p; }" : "=r"(done) : "r"(a), "r"(parity) : "memory");
    if (!done) {
        asm volatile(
            "{ .reg .pred P1;\n\t"
            "WL%=:\n\t"
            "mbarrier.try_wait.parity.acquire.cta.shared::cta.b64 P1, [%0], %1, 0x989680;\n\t"
            "@P1 bra WD%=;\n\t"
            "bra WL%=;\n\t"
            "WD%=:\n\t}" :: "r"(a), "r"(parity) : "memory");
    }
}

#if HAS_TC
#define TC_ALLOC(sa, n)   asm volatile("tcgen05.alloc.cta_group::1.sync.aligned.shared::cta.b32 [%0], %1;" :: "r"(sa), "r"(n) : "memory")
#define TC_RELINQ()       asm volatile("tcgen05.relinquish_alloc_permit.cta_group::1.sync.aligned;")
#define TC_DEALLOC(t, n)  asm volatile("tcgen05.dealloc.cta_group::1.sync.aligned.b32 %0, %1;" :: "r"(t), "r"(n))
#define TC_COMMIT(mb)     asm volatile("tcgen05.commit.cta_group::1.mbarrier::arrive::one.shared::cluster.b64 [%0];" :: "r"(mb) : "memory")
#define TC_FENCE_AFTER()  asm volatile("tcgen05.fence::after_thread_sync;" ::: "memory")
#define TC_FENCE_BEFORE() asm volatile("tcgen05.fence::before_thread_sync;" ::: "memory")
#define TC_WAIT_LD()      asm volatile("tcgen05.wait::ld.sync.aligned;" ::: "memory")
#define TC_LD_X32(r, ta) \
    asm volatile( \
        "tcgen05.ld.sync.aligned.32x32b.x32.b32 " \
        "{%0, %1, %2, %3, %4, %5, %6, %7, " \
        " %8, %9, %10, %11, %12, %13, %14, %15, " \
        " %16, %17, %18, %19, %20, %21, %22, %23, " \
        " %24, %25, %26, %27, %28, %29, %30, %31}, [%32];" \
        : "=r"((r)[0]),  "=r"((r)[1]),  "=r"((r)[2]),  "=r"((r)[3]), \
          "=r"((r)[4]),  "=r"((r)[5]),  "=r"((r)[6]),  "=r"((r)[7]), \
          "=r"((r)[8]),  "=r"((r)[9]),  "=r"((r)[10]), "=r"((r)[11]), \
          "=r"((r)[12]), "=r"((r)[13]), "=r"((r)[14]), "=r"((r)[15]), \
          "=r"((r)[16]), "=r"((r)[17]), "=r"((r)[18]), "=r"((r)[19]), \
          "=r"((r)[20]), "=r"((r)[21]), "=r"((r)[22]), "=r"((r)[23]), \
          "=r"((r)[24]), "=r"((r)[25]), "=r"((r)[26]), "=r"((r)[27]), \
          "=r"((r)[28]), "=r"((r)[29]), "=r"((r)[30]), "=r"((r)[31]) \
        : "r"(ta))
#else
#define TC_ALLOC(sa, n)   ((void)0)
#define TC_RELINQ()       ((void)0)
#define TC_DEALLOC(t, n)  ((void)0)
#define TC_COMMIT(mb)     ((void)0)
#define TC_FENCE_AFTER()  ((void)0)
#define TC_FENCE_BEFORE() ((void)0)
#define TC_WAIT_LD()      ((void)0)
#define TC_LD_X32(r, ta)  do { _Pragma("unroll") for (int _i = 0; _i < 32; ++_i) (r)[_i] = 0u; } while (0)
#endif
#define FENCE_ASYNC()     asm volatile("fence.proxy.async.shared::cta;" ::: "memory")

static __device__ __forceinline__ void a_store(char* Ahi, char* Alo, int r, int k, float v) {
    __nv_bfloat16 h = __float2bfloat16(v);
    float l = v - __bfloat162float(h);
    uint32_t o = tile_off(r, k);
    *(__nv_bfloat16*)(Ahi + o) = h;
    *(__nv_bfloat16*)(Alo + o) = __float2bfloat16(l);
}

// -------------------------------------------------------------- prepass -----
// Layer chunk bases (16KB chunks): L0@0(4), L1@4, L2@20, L3@36, L4@52,
// L5@68(20), L6@88, L7@104, L8@120(20). Total 140.
__global__ void nerf_prepass(
    const float* W0, const float* W1, const float* W2, const float* W3, const float* W4,
    const float* W5, const float* W6, const float* W7, const float* W8)
{
    int layer = blockIdx.y;
    int k = blockIdx.x;           // padded K index within layer
    int n = threadIdx.x;          // output neuron 0..255
    const float* W; int Kpad, kaoff, kalen, kblen; uint32_t cbase;
    switch (layer) {
        case 0: W = W0; Kpad = 64;  kaoff = 0;  kalen = 63;  kblen = 0;   cbase = 0;   break;
        case 1: W = W1; Kpad = 256; kaoff = 0;  kalen = 256; kblen = 0;   cbase = 4;   break;
        case 2: W = W2; Kpad = 256; kaoff = 0;  kalen = 256; kblen = 0;   cbase = 20;  break;
        case 3: W = W3; Kpad = 256; kaoff = 0;  kalen = 256; kblen = 0;   cbase = 36;  break;
        case 4: W = W4; Kpad = 256; kaoff = 0;  kalen = 256; kblen = 0;   cbase = 52;  break;
        case 5: W = W5; Kpad = 320; kaoff = 0;  kalen = 63;  kblen = 256; cbase = 68;  break;
        case 6: W = W6; Kpad = 256; kaoff = 0;  kalen = 256; kblen = 0;   cbase = 88;  break;
        case 7: W = W7; Kpad = 256; kaoff = 0;  kalen = 256; kblen = 0;   cbase = 104; break;
        default: W = W8; Kpad = 320; kaoff = 24; kalen = 39; kblen = 256; cbase = 120; break;
    }
    if (k >= Kpad) return;
    int row = -1;
    if (k >= kaoff && k < kaoff + kalen) row = k - kaoff;
    else if (kblen && k >= 64 && k < 64 + kblen) row = kalen + (k - 64);
    float v = (row >= 0) ? W[(size_t)row * 256 + n] : 0.f;

    uint32_t off = (cbase + (uint32_t)(k >> 4)) * CH_BYTES;
    int local = k & 15;
    __nv_bfloat16 h = __float2bfloat16(v);
    float l = v - __bfloat162float(h);
    *(__nv_bfloat16*)(g_wscratch + off + b_off64(n, local))      = h;
    *(__nv_bfloat16*)(g_wscratch + off + b_off64(n, 16 + local)) = __float2bfloat16(l);
}

// ------------------------------------------------------------- run_layer ----
struct Pipe { int gmma, gcopy, lpar; int pf[4], pm[4]; };

static __device__ __noinline__ void run_layer(
    char* smem, uint32_t sb, uint32_t tmem,
    int nch, int a_step0, int d_off,
    const float* __restrict__ bias, int relu, int do_epi, Pipe& pp)
{
    const int tid = threadIdx.x;
    const int w = tid >> 5;
    __syncthreads();   // prev epilogue / PE A-writes (fenced per-thread) done

    if (tid == 0) {
        const uint64_t adh = mkdesc128(sb + AHI_OFF);
        const uint64_t adl = mkdesc128(sb + ALO_OFF);
        for (int i = 0; i < nch; ++i, ++pp.gmma) {
            const int g = pp.gmma;
            const int buf = g & 3;
            mbar_wait(sb + MBAR_OFF + buf * 8, (uint32_t)pp.pf[buf]);
            pp.pf[buf] ^= 1;
            const uint64_t bd = mkdesc64(sb + B_OFF + (uint32_t)buf * CH_BYTES);
            const int s = a_step0 + i;
            const uint64_t aoff = (uint64_t)((s >> 2) * 1024 + (s & 3) * 2);
            mma_ss(tmem + d_off, adh + aoff, bd,     i > 0);  // Ahi*Bhi
            mma_ss(tmem + d_off, adh + aoff, bd + 2, 1u);     // Ahi*Blo
            mma_ss(tmem + d_off, adl + aoff, bd,     1u);     // Alo*Bhi
            TC_COMMIT(sb + MBAR_OFF + 32 + buf * 8);
            const int t = pp.gcopy;
            if (t < NCH_TOTAL) {
                const int cb = t & 3;
                if (t >= 4) {   // free-wait: chunk t-4 used this buffer
                    mbar_wait(sb + MBAR_OFF + 32 + cb * 8, (uint32_t)pp.pm[cb]);
                    pp.pm[cb] ^= 1;
                }
                mbar_expect_tx(sb + MBAR_OFF + cb * 8, CH_BYTES);
                bulk_copy16k(sb + B_OFF + (uint32_t)cb * CH_BYTES,
                             g_wscratch + (uint32_t)t * CH_BYTES,
                             sb + MBAR_OFF + cb * 8);
                pp.gcopy = t + 1;
            }
        }
        TC_COMMIT(sb + MBAR_OFF + 64);   // layer-done barrier
    }
    // all threads: wait layer completion
    mbar_wait(sb + MBAR_OFF + 64, (uint32_t)pp.lpar);
    pp.lpar ^= 1;
    TC_FENCE_AFTER();
    if (!do_epi) return;

    const int lane = tid & 31;
    const int r  = (w & 3) * 32 + lane;
    const int c0 = (w >> 2) * 64;
    char* Ahi = smem + AHI_OFF;
    char* Alo = smem + ALO_OFF;

    #pragma unroll
    for (int h = 0; h < 2; ++h) {
        uint32_t rg[32];
        TC_LD_X32(rg, tmem + d_off + c0 + h * 32);
        TC_WAIT_LD();
        const int kb = c0 + h * 32;
        #pragma unroll
        for (int q = 0; q < 4; ++q) {
            float4 b0 = __ldg((const float4*)(bias + kb + q * 8));
            float4 b1 = __ldg((const float4*)(bias + kb + q * 8 + 4));
            float v[8];
            v[0] = __uint_as_float(rg[q * 8 + 0]) + b0.x;
            v[1] = __uint_as_float(rg[q * 8 + 1]) + b0.y;
            v[2] = __uint_as_float(rg[q * 8 + 2]) + b0.z;
            v[3] = __uint_as_float(rg[q * 8 + 3]) + b0.w;
            v[4] = __uint_as_float(rg[q * 8 + 4]) + b1.x;
            v[5] = __uint_as_float(rg[q * 8 + 5]) + b1.y;
            v[6] = __uint_as_float(rg[q * 8 + 6]) + b1.z;
            v[7] = __uint_as_float(rg[q * 8 + 7]) + b1.w;
            if (relu) {
                #pragma unroll
                for (int e = 0; e < 8; ++e) v[e] = fmaxf(v[e], 0.f);
            }
            uint32_t hp[4], lp[4];
            #pragma unroll
            for (int e = 0; e < 4; ++e) {
                __nv_bfloat16 h0 = __float2bfloat16(v[2 * e]);
                __nv_bfloat16 h1 = __float2bfloat16(v[2 * e + 1]);
                float l0 = v[2 * e]     - __bfloat162float(h0);
                float l1 = v[2 * e + 1] - __bfloat162float(h1);
                __nv_bfloat16 g0 = __float2bfloat16(l0);
                __nv_bfloat16 g1 = __float2bfloat16(l1);
                hp[e] = (uint32_t)__bfloat16_as_ushort(h0) | ((uint32_t)__bfloat16_as_ushort(h1) << 16);
                lp[e] = (uint32_t)__bfloat16_as_ushort(g0) | ((uint32_t)__bfloat16_as_ushort(g1) << 16);
            }
            uint32_t off = tile_off(r, 64 + kb + q * 8);
            *(uint4*)(Ahi + off) = make_uint4(hp[0], hp[1], hp[2], hp[3]);
            *(uint4*)(Alo + off) = make_uint4(lp[0], lp[1], lp[2], lp[3]);
        }
    }
    TC_FENCE_BEFORE();
    FENCE_ASYNC();     // epilogue A-writes visible to async proxy
}

// ----------------------------------------------------------- main kernel ----
__global__ void __launch_bounds__(TPB, 1) nerf_main(
    const float* __restrict__ x, const float* __restrict__ dirg,
    const float* g1_0_b, const float* g1_1_b, const float* g1_2_b,
    const float* g1_3_b, const float* g1_4_b,
    const float* g2_0_b, const float* g2_1_b, const float* g2_2_b,
    const float* c_0_b,  const float* c_1_W,  const float* c_1_b,
    const float* sig_W,  const float* sig_b,
    float* __restrict__ out)
{
    extern __shared__ __align__(1024) char smem[];
    const uint32_t sb = smem_u32(smem);
    const int tid = threadIdx.x;
    const int w = tid >> 5, lane = tid & 31;
    char* Ahi = smem + AHI_OFF;
    char* Alo = smem + ALO_OFF;

    if (w == 0) { TC_ALLOC(sb + TMEMP_OFF, 512); TC_RELINQ(); }
    if (tid == 0) {
        #pragma unroll
        for (int b = 0; b < 4; ++b) {
            mbar_init(sb + MBAR_OFF + b * 8, 1);        // full[b]
            mbar_init(sb + MBAR_OFF + 32 + b * 8, 1);   // mma[b]
        }
        mbar_init(sb + MBAR_OFF + 64, 1);               // layer
        FENCE_ASYNC();
        // prologue: chunks 0,1,2 in flight during PE computation
        #pragma unroll
        for (int b = 0; b < 3; ++b) {
            mbar_expect_tx(sb + MBAR_OFF + b * 8, CH_BYTES);
            bulk_copy16k(sb + B_OFF + (uint32_t)b * CH_BYTES,
                         g_wscratch + (uint32_t)b * CH_BYTES,
                         sb + MBAR_OFF + b * 8);
        }
    }
    __syncthreads();
    uint32_t tmem;
    asm volatile("ld.shared.b32 %0, [%1];" : "=r"(tmem) : "r"(sb + TMEMP_OFF));

    const int row0 = blockIdx.x * MROWS;
    const int r = tid >> 2, p = tid & 3;

    if (tid < 128) a_store(Ahi, Alo, tid, 63, 0.f);

    {
        const float* xr = x + (size_t)(row0 + r) * 3;
        float x0 = xr[0], x1 = xr[1], x2 = xr[2];
        if (p == 0) {
            a_store(Ahi, Alo, r, 0, x0);
            a_store(Ahi, Alo, r, 1, x1);
            a_store(Ahi, Alo, r, 2, x2);
        }
        for (int l = p; l < 10; l += 4) {
            float f = (float)(1 << l);
            float s, c;
            sincosf(x0 * f, &s, &c); a_store(Ahi, Alo, r, 3 + 6 * l + 0, s); a_store(Ahi, Alo, r, 6 + 6 * l + 0, c);
            sincosf(x1 * f, &s, &c); a_store(Ahi, Alo, r, 3 + 6 * l + 1, s); a_store(Ahi, Alo, r, 6 + 6 * l + 1, c);
            sincosf(x2 * f, &s, &c); a_store(Ahi, Alo, r, 3 + 6 * l + 2, s); a_store(Ahi, Alo, r, 6 + 6 * l + 2, c);
        }
    }
    FENCE_ASYNC();

    Pipe pp;
    pp.gmma = 0; pp.gcopy = 3; pp.lpar = 0;
    #pragma unroll
    for (int b = 0; b < 4; ++b) { pp.pf[b] = 0; pp.pm[b] = 0; }

    run_layer(smem, sb, tmem,  4, 0, D1, g1_0_b, 1, 1, pp);
    run_layer(smem, sb, tmem, 16, 4, D1, g1_1_b, 1, 1, pp);
    run_layer(smem, sb, tmem, 16, 4, D1, g1_2_b, 1, 1, pp);
    run_layer(smem, sb, tmem, 16, 4, D1, g1_3_b, 1, 1, pp);
    run_layer(smem, sb, tmem, 16, 4, D1, g1_4_b, 0, 1, pp);
    run_layer(smem, sb, tmem, 20, 0, D1, g2_0_b, 1, 1, pp);

    // pe_d -> cols [24,63): safe, g2_0's layer barrier completed all its MMAs.
    {
        const float* dr = dirg + (size_t)(row0 + r) * 3;
        float d0 = dr[0], d1 = dr[1], d2 = dr[2];
        if (p == 0) {
            a_store(Ahi, Alo, r, 24, d0);
            a_store(Ahi, Alo, r, 25, d1);
            a_store(Ahi, Alo, r, 26, d2);
        }
        for (int l = p; l < 6; l += 4) {
            float f = (float)(1 << l);
            float s, c;
            sincosf(d0 * f, &s, &c); a_store(Ahi, Alo, r, 27 + 6 * l + 0, s); a_store(Ahi, Alo, r, 30 + 6 * l + 0, c);
            sincosf(d1 * f, &s, &c); a_store(Ahi, Alo, r, 27 + 6 * l + 1, s); a_store(Ahi, Alo, r, 30 + 6 * l + 1, c);
            sincosf(d2 * f, &s, &c); a_store(Ahi, Alo, r, 27 + 6 * l + 2, s); a_store(Ahi, Alo, r, 30 + 6 * l + 2, c);
        }
        FENCE_ASYNC();
    }

    run_layer(smem, sb, tmem, 16, 4, D1, g2_1_b, 1, 1, pp);
    run_layer(smem, sb, tmem, 16, 4, D2, g2_2_b, 0, 1, pp);   // features2 -> D2 (preact)
    run_layer(smem, sb, tmem, 20, 0, D1, c_0_b,  0, 0, pp);   // c_0 preact -> D1

    __syncthreads();
    TC_FENCE_AFTER();

    // stage head params into (now-idle) B region
    float* SWM = (float*)(smem + B_OFF);
    for (int i = tid; i < 256; i += TPB) {
        SWM[i]        = sig_W[i];
        SWM[256 + i]  = c_0_b[i];
        SWM[1536 + i] = g2_2_b[i];
    }
    for (int i = tid; i < 768; i += TPB) SWM[512 + i] = c_1_W[i];
    if (tid == 0) {
        SWM[1280] = sig_b[0];
        SWM[1281] = c_1_b[0]; SWM[1282] = c_1_b[1]; SWM[1283] = c_1_b[2];
    }
    __syncthreads();

    // heads: sigma = (D2 + g2_2_b) . sig_W + sig_b ; rgb = relu(D1 + c_0_b) @ c_1
    if (w < 4) {
        const int rr = w * 32 + lane;
        float sig = 0.f;
        for (int blk = 0; blk < 8; ++blk) {
            uint32_t rg[32];
            TC_LD_X32(rg, tmem + D2 + blk * 32);
            TC_WAIT_LD();
            #pragma unroll
            for (int i = 0; i < 32; ++i) {
                int k = blk * 32 + i;
                sig += (__uint_as_float(rg[i]) + SWM[1536 + k]) * SWM[k];
            }
        }
        float o0 = 0.f, o1 = 0.f, o2 = 0.f;
        for (int blk = 0; blk < 8; ++blk) {
            uint32_t rg[32];
            TC_LD_X32(rg, tmem + D1 + blk * 32);
            TC_WAIT_LD();
            #pragma unroll
            for (int i = 0; i < 32; ++i) {
                int k = blk * 32 + i;
                float f = fmaxf(__uint_as_float(rg[i]) + SWM[256 + k], 0.f);
                o0 += f * SWM[512 + 3 * k + 0];
                o1 += f * SWM[512 + 3 * k + 1];
                o2 += f * SWM[512 + 3 * k + 2];
            }
        }
        float4 o = make_float4(o0 + SWM[1281], o1 + SWM[1282], o2 + SWM[1283], sig + SWM[1280]);
        *(float4*)(out + (size_t)(row0 + rr) * 4) = o;
        TC_FENCE_BEFORE();
    }
    __syncthreads();
    if (w == 0) TC_DEALLOC(tmem, 512);
}

// ---------------------------------------------------------------- launch ----
extern "C" void kernel_launch(void* const* d_in, const int* in_sizes, int n_in,
                              void* d_out, int out_size)
{
    const float* x      = (const float*)d_in[0];
    const float* dirg   = (const float*)d_in[1];
    const float* g1_0_W = (const float*)d_in[2];  const float* g1_0_b = (const float*)d_in[3];
    const float* g1_1_W = (const float*)d_in[4];  const float* g1_1_b = (const float*)d_in[5];
    const float* g1_2_W = (const float*)d_in[6];  const float* g1_2_b = (const float*)d_in[7];
    const float* g1_3_W = (const float*)d_in[8];  const float* g1_3_b = (const float*)d_in[9];
    const float* g1_4_W = (const float*)d_in[10]; const float* g1_4_b = (const float*)d_in[11];
    const float* g2_0_W = (const float*)d_in[12]; const float* g2_0_b = (const float*)d_in[13];
    const float* g2_1_W = (const float*)d_in[14]; const float* g2_1_b = (const float*)d_in[15];
    const float* g2_2_W = (const float*)d_in[16]; const float* g2_2_b = (const float*)d_in[17];
    const float* c_0_W  = (const float*)d_in[18]; const float* c_0_b  = (const float*)d_in[19];
    const float* c_1_W  = (const float*)d_in[20]; const float* c_1_b  = (const float*)d_in[21];
    const float* sig_W  = (const float*)d_in[22]; const float* sig_b  = (const float*)d_in[23];
    float* out = (float*)d_out;

    const int N = in_sizes[0] / 3;           // 262144
    const int nblocks = N / MROWS;           // 2048

    dim3 pgrid(320, 9);
    nerf_prepass<<<pgrid, 256>>>(g1_0_W, g1_1_W, g1_2_W, g1_3_W, g1_4_W,
                                 g2_0_W, g2_1_W, g2_2_W, c_0_W);

    cudaFuncSetAttribute(nerf_main, cudaFuncAttributeMaxDynamicSharedMemorySize, SMEM_BYTES);
    nerf_main<<<nblocks, TPB, SMEM_BYTES>>>(
        x, dirg,
        g1_0_b, g1_1_b, g1_2_b, g1_3_b, g1_4_b,
        g2_0_b, g2_1_b, g2_2_b,
        c_0_b, c_1_W, c_1_b,
        sig_W, sig_b,
        out);
}

// round 12
// speedup vs baseline: 1.3053x; 1.3053x over previous
#include <cuda_runtime.h>
#include <cuda_bf16.h>
#include <cstdint>

// ============================================================================
// NeRF fused MLP on tcgen05 (bf16 2-term split, fp32 TMEM accumulate).
// R12: warp-specialized pipeline — MMA issuer (tid 0) and copy producer
// (tid 32) run independently over a flat 140-chunk schedule, 4x16KB SW64
// B buffers, prefetch distance 3.
//
// Scratch: 140 consecutive 16KB chunk frames (one per K16 step of every
// layer). Frame = 256 N-rows x 64B SW64: bf16 hi at frame K-cols [0,16),
// lo at [16,32). Copy = one cp.async.bulk of 16KB.
//   tid 0  per chunk g: wait full[g%4] (fast path) -> 3 MMAs (hh, Ahi*Blo,
//          Alo*Bhi) -> commit mma[g%4]. Paced by tcgen05 queue backpressure.
//   tid 32 per chunk t: wait mma[t%4] (chunk t-4 drained -> buffer free) ->
//          expect_tx -> bulk-copy chunk t. Blocking waits overlap tid 0.
// Layer completion via a dedicated commit barrier; epilogue: LDTM f32 +
// bias + ReLU, re-split bf16 hi/lo to SW128 A tiles. Copies run 3 chunks
// ahead so next layer's weights land during the epilogue.
//
// tcgen05 asm guarded by HAS_TC (generic compute_103 PTX variant must not
// contain it; never executed). cp.async.bulk/mbarrier are sm_90 baseline.
// ============================================================================

#if defined(__CUDA_ARCH_FEAT_SM103_ALL) || defined(__CUDA_ARCH_FEAT_SM100_ALL) || defined(__CUDA_ARCH_FEAT_SM101_ALL)
#define HAS_TC 1
#else
#define HAS_TC 0
#endif

#define TPB        512
#define MROWS      128
#define AHI_OFF    0
#define ALO_OFF    81920
#define B_OFF      163840            // 4 x 16KB buffers
#define TMEMP_OFF  229376
#define MBAR_OFF   229384            // full[4]@+0..31, mma[4]@+32..63, layer@+64
#define SMEM_BYTES 229456
#define D1         0
#define D2         256
#define CH_BYTES   16384u
#define NCH_TOTAL  140
// idesc kind::f16: dtype=F32(1<<4), a=BF16(1<<7), b=BF16(1<<10), N=256, M=128
#define IDESC      0x8400490u
#define WSCRATCH_BYTES (NCH_TOTAL * CH_BYTES)

__device__ __align__(128) unsigned char g_wscratch[WSCRATCH_BYTES];

static __device__ __forceinline__ uint32_t swz128(uint32_t b) { return b ^ ((b >> 3) & 0x70); }
static __device__ __forceinline__ uint32_t swz64(uint32_t b)  { return b ^ ((b >> 3) & 0x30); }
// A tile (SW128 blocked atoms, 128 rows x 320 K-cols)
static __device__ __forceinline__ uint32_t tile_off(int r, int k) {
    return (uint32_t)(((k >> 6) * 16 + (r >> 3)) * 1024)
         + swz128((uint32_t)(((r & 7) << 7) | ((k & 63) << 1)));
}
// B chunk frame (SW64, 256 rows x 32 cols bf16 = 64B rows)
static __device__ __forceinline__ uint32_t b_off64(int n, int c) {
    return (uint32_t)((n >> 3) * 512)
         + swz64((uint32_t)(((n & 7) << 6) | (c << 1)));
}
static __device__ __forceinline__ uint32_t smem_u32(const void* p) {
    uint32_t a;
    asm("{ .reg .u64 t; cvta.to.shared.u64 t, %1; cvt.u32.u64 %0, t; }" : "=r"(a) : "l"(p));
    return a;
}
static __device__ __forceinline__ uint64_t mkdesc128(uint32_t addr) {
    const uint64_t base = (uint64_t(2) << 61) | (uint64_t(1) << 46)
                        | (uint64_t(64) << 32) | (uint64_t(1) << 16);
    return base | ((uint64_t)(addr >> 4) & 0x3FFF);
}
static __device__ __forceinline__ uint64_t mkdesc64(uint32_t addr) {
    const uint64_t base = (uint64_t(4) << 61) | (uint64_t(1) << 46)
                        | (uint64_t(32) << 32) | (uint64_t(1) << 16);
    return base | ((uint64_t)(addr >> 4) & 0x3FFF);
}

static __device__ __forceinline__ void mma_ss(uint32_t d, uint64_t ad, uint64_t bd, uint32_t en) {
#if HAS_TC
    asm volatile(
        "{ .reg .pred p; setp.ne.u32 p, %5, 0;\n\t"
        "tcgen05.mma.cta_group::1.kind::f16 [%0], %1, %2, %3, {%4,%4,%4,%4}, p; }"
        :: "r"(d), "l"(ad), "l"(bd), "r"(IDESC), "r"(0u), "r"(en) : "memory");
#endif
}
static __device__ __forceinline__ void mbar_init(uint32_t a, uint32_t cnt) {
    asm volatile("mbarrier.init.shared.b64 [%0], %1;" :: "r"(a), "r"(cnt) : "memory");
}
static __device__ __forceinline__ void mbar_expect_tx(uint32_t a, uint32_t bytes) {
    asm volatile("mbarrier.arrive.expect_tx.shared.b64 _, [%0], %1;" :: "r"(a), "r"(bytes) : "memory");
}
static __device__ __forceinline__ void bulk_copy16k(uint32_t dst, const void* src, uint32_t mbar) {
    asm volatile(
        "cp.async.bulk.shared::cluster.global.mbarrier::complete_tx::bytes [%0], [%1], %2, [%3];"
        :: "r"(dst), "l"(src), "r"(CH_BYTES), "r"(mbar) : "memory");
}
static __device__ __forceinline__ void mbar_wait(uint32_t a, uint32_t parity) {
    uint32_t done;
    asm volatile(
        "{ .reg .pred p; mbarrier.try_wait.parity.acquire.cta.shared::cta.b64 p, [%1], %2;"
        " selp.b32 %0, 1, 0, p; }" : "=r"(done) : "r"(a), "r"(parity) : "memory");
    if (!done) {
        asm volatile(
            "{ .reg .pred P1;\n\t"
            "WL%=:\n\t"
            "mbarrier.try_wait.parity.acquire.cta.shared::cta.b64 P1, [%0], %1, 0x989680;\n\t"
            "@P1 bra WD%=;\n\t"
            "bra WL%=;\n\t"
            "WD%=:\n\t}" :: "r"(a), "r"(parity) : "memory");
    }
}

#if HAS_TC
#define TC_ALLOC(sa, n)   asm volatile("tcgen05.alloc.cta_group::1.sync.aligned.shared::cta.b32 [%0], %1;" :: "r"(sa), "r"(n) : "memory")
#define TC_RELINQ()       asm volatile("tcgen05.relinquish_alloc_permit.cta_group::1.sync.aligned;")
#define TC_DEALLOC(t, n)  asm volatile("tcgen05.dealloc.cta_group::1.sync.aligned.b32 %0, %1;" :: "r"(t), "r"(n))
#define TC_COMMIT(mb)     asm volatile("tcgen05.commit.cta_group::1.mbarrier::arrive::one.shared::cluster.b64 [%0];" :: "r"(mb) : "memory")
#define TC_FENCE_AFTER()  asm volatile("tcgen05.fence::after_thread_sync;" ::: "memory")
#define TC_FENCE_BEFORE() asm volatile("tcgen05.fence::before_thread_sync;" ::: "memory")
#define TC_WAIT_LD()      asm volatile("tcgen05.wait::ld.sync.aligned;" ::: "memory")
#define TC_LD_X32(r, ta) \
    asm volatile( \
        "tcgen05.ld.sync.aligned.32x32b.x32.b32 " \
        "{%0, %1, %2, %3, %4, %5, %6, %7, " \
        " %8, %9, %10, %11, %12, %13, %14, %15, " \
        " %16, %17, %18, %19, %20, %21, %22, %23, " \
        " %24, %25, %26, %27, %28, %29, %30, %31}, [%32];" \
        : "=r"((r)[0]),  "=r"((r)[1]),  "=r"((r)[2]),  "=r"((r)[3]), \
          "=r"((r)[4]),  "=r"((r)[5]),  "=r"((r)[6]),  "=r"((r)[7]), \
          "=r"((r)[8]),  "=r"((r)[9]),  "=r"((r)[10]), "=r"((r)[11]), \
          "=r"((r)[12]), "=r"((r)[13]), "=r"((r)[14]), "=r"((r)[15]), \
          "=r"((r)[16]), "=r"((r)[17]), "=r"((r)[18]), "=r"((r)[19]), \
          "=r"((r)[20]), "=r"((r)[21]), "=r"((r)[22]), "=r"((r)[23]), \
          "=r"((r)[24]), "=r"((r)[25]), "=r"((r)[26]), "=r"((r)[27]), \
          "=r"((r)[28]), "=r"((r)[29]), "=r"((r)[30]), "=r"((r)[31]) \
        : "r"(ta))
#else
#define TC_ALLOC(sa, n)   ((void)0)
#define TC_RELINQ()       ((void)0)
#define TC_DEALLOC(t, n)  ((void)0)
#define TC_COMMIT(mb)     ((void)0)
#define TC_FENCE_AFTER()  ((void)0)
#define TC_FENCE_BEFORE() ((void)0)
#define TC_WAIT_LD()      ((void)0)
#define TC_LD_X32(r, ta)  do { _Pragma("unroll") for (int _i = 0; _i < 32; ++_i) (r)[_i] = 0u; } while (0)
#endif
#define FENCE_ASYNC()     asm volatile("fence.proxy.async.shared::cta;" ::: "memory")

static __device__ __forceinline__ void a_store(char* Ahi, char* Alo, int r, int k, float v) {
    __nv_bfloat16 h = __float2bfloat16(v);
    float l = v - __bfloat162float(h);
    uint32_t o = tile_off(r, k);
    *(__nv_bfloat16*)(Ahi + o) = h;
    *(__nv_bfloat16*)(Alo + o) = __float2bfloat16(l);
}

// -------------------------------------------------------------- prepass -----
// Layer chunk bases (16KB chunks): L0@0(4), L1@4, L2@20, L3@36, L4@52,
// L5@68(20), L6@88, L7@104, L8@120(20). Total 140.
__global__ void nerf_prepass(
    const float* W0, const float* W1, const float* W2, const float* W3, const float* W4,
    const float* W5, const float* W6, const float* W7, const float* W8)
{
    int layer = blockIdx.y;
    int k = blockIdx.x;           // padded K index within layer
    int n = threadIdx.x;          // output neuron 0..255
    const float* W; int Kpad, kaoff, kalen, kblen; uint32_t cbase;
    switch (layer) {
        case 0: W = W0; Kpad = 64;  kaoff = 0;  kalen = 63;  kblen = 0;   cbase = 0;   break;
        case 1: W = W1; Kpad = 256; kaoff = 0;  kalen = 256; kblen = 0;   cbase = 4;   break;
        case 2: W = W2; Kpad = 256; kaoff = 0;  kalen = 256; kblen = 0;   cbase = 20;  break;
        case 3: W = W3; Kpad = 256; kaoff = 0;  kalen = 256; kblen = 0;   cbase = 36;  break;
        case 4: W = W4; Kpad = 256; kaoff = 0;  kalen = 256; kblen = 0;   cbase = 52;  break;
        case 5: W = W5; Kpad = 320; kaoff = 0;  kalen = 63;  kblen = 256; cbase = 68;  break;
        case 6: W = W6; Kpad = 256; kaoff = 0;  kalen = 256; kblen = 0;   cbase = 88;  break;
        case 7: W = W7; Kpad = 256; kaoff = 0;  kalen = 256; kblen = 0;   cbase = 104; break;
        default: W = W8; Kpad = 320; kaoff = 24; kalen = 39; kblen = 256; cbase = 120; break;
    }
    if (k >= Kpad) return;
    int row = -1;
    if (k >= kaoff && k < kaoff + kalen) row = k - kaoff;
    else if (kblen && k >= 64 && k < 64 + kblen) row = kalen + (k - 64);
    float v = (row >= 0) ? W[(size_t)row * 256 + n] : 0.f;

    uint32_t off = (cbase + (uint32_t)(k >> 4)) * CH_BYTES;
    int local = k & 15;
    __nv_bfloat16 h = __float2bfloat16(v);
    float l = v - __bfloat162float(h);
    *(__nv_bfloat16*)(g_wscratch + off + b_off64(n, local))      = h;
    *(__nv_bfloat16*)(g_wscratch + off + b_off64(n, 16 + local)) = __float2bfloat16(l);
}

// ------------------------------------------------------------- run_layer ----
struct Pipe { int gmma, gcopy, lpar; int pf[4], pm[4]; };

static __device__ __noinline__ void run_layer(
    char* smem, uint32_t sb, uint32_t tmem,
    int nch, int a_step0, int d_off,
    const float* __restrict__ bias, int relu, int do_epi, Pipe& pp)
{
    const int tid = threadIdx.x;
    const int w = tid >> 5;
    __syncthreads();   // prev epilogue / PE A-writes (fenced per-thread) done

    if (tid == 0) {
        // ---- MMA issuer: no free-waits, no copies; paced by tcgen05 queue.
        const uint64_t adh = mkdesc128(sb + AHI_OFF);
        const uint64_t adl = mkdesc128(sb + ALO_OFF);
        uint64_t bds[4];
        #pragma unroll
        for (int b = 0; b < 4; ++b) bds[b] = mkdesc64(sb + B_OFF + (uint32_t)b * CH_BYTES);
        for (int i = 0; i < nch; ++i) {
            const int g = pp.gmma++;
            const int buf = g & 3;
            mbar_wait(sb + MBAR_OFF + buf * 8, (uint32_t)pp.pf[buf]);
            pp.pf[buf] ^= 1;
            const int s = a_step0 + i;
            const uint64_t aoff = (uint64_t)((s >> 2) * 1024 + (s & 3) * 2);
            mma_ss(tmem + d_off, adh + aoff, bds[buf],     i > 0);  // Ahi*Bhi
            mma_ss(tmem + d_off, adh + aoff, bds[buf] + 2, 1u);     // Ahi*Blo
            mma_ss(tmem + d_off, adl + aoff, bds[buf],     1u);     // Alo*Bhi
            TC_COMMIT(sb + MBAR_OFF + 32 + buf * 8);
        }
        TC_COMMIT(sb + MBAR_OFF + 64);   // layer-done barrier
    } else if (tid == 32) {
        // ---- Copy producer: frees buffers + streams chunks, fully overlapped.
        for (int i = 0; i < nch; ++i) {
            const int t = pp.gcopy;
            if (t >= NCH_TOTAL) break;
            const int cb = t & 3;
            if (t >= 4) {   // chunk t-4 used this buffer; wait its MMAs drained
                mbar_wait(sb + MBAR_OFF + 32 + cb * 8, (uint32_t)pp.pm[cb]);
                pp.pm[cb] ^= 1;
            }
            mbar_expect_tx(sb + MBAR_OFF + cb * 8, CH_BYTES);
            bulk_copy16k(sb + B_OFF + (uint32_t)cb * CH_BYTES,
                         g_wscratch + (uint32_t)t * CH_BYTES,
                         sb + MBAR_OFF + cb * 8);
            pp.gcopy = t + 1;
        }
    }
    // all threads: wait layer completion
    mbar_wait(sb + MBAR_OFF + 64, (uint32_t)pp.lpar);
    pp.lpar ^= 1;
    TC_FENCE_AFTER();
    if (!do_epi) return;

    const int lane = tid & 31;
    const int r  = (w & 3) * 32 + lane;
    const int c0 = (w >> 2) * 64;
    char* Ahi = smem + AHI_OFF;
    char* Alo = smem + ALO_OFF;

    #pragma unroll
    for (int h = 0; h < 2; ++h) {
        uint32_t rg[32];
        TC_LD_X32(rg, tmem + d_off + c0 + h * 32);
        TC_WAIT_LD();
        const int kb = c0 + h * 32;
        #pragma unroll
        for (int q = 0; q < 4; ++q) {
            float4 b0 = __ldg((const float4*)(bias + kb + q * 8));
            float4 b1 = __ldg((const float4*)(bias + kb + q * 8 + 4));
            float v[8];
            v[0] = __uint_as_float(rg[q * 8 + 0]) + b0.x;
            v[1] = __uint_as_float(rg[q * 8 + 1]) + b0.y;
            v[2] = __uint_as_float(rg[q * 8 + 2]) + b0.z;
            v[3] = __uint_as_float(rg[q * 8 + 3]) + b0.w;
            v[4] = __uint_as_float(rg[q * 8 + 4]) + b1.x;
            v[5] = __uint_as_float(rg[q * 8 + 5]) + b1.y;
            v[6] = __uint_as_float(rg[q * 8 + 6]) + b1.z;
            v[7] = __uint_as_float(rg[q * 8 + 7]) + b1.w;
            if (relu) {
                #pragma unroll
                for (int e = 0; e < 8; ++e) v[e] = fmaxf(v[e], 0.f);
            }
            uint32_t hp[4], lp[4];
            #pragma unroll
            for (int e = 0; e < 4; ++e) {
                __nv_bfloat16 h0 = __float2bfloat16(v[2 * e]);
                __nv_bfloat16 h1 = __float2bfloat16(v[2 * e + 1]);
                float l0 = v[2 * e]     - __bfloat162float(h0);
                float l1 = v[2 * e + 1] - __bfloat162float(h1);
                __nv_bfloat16 g0 = __float2bfloat16(l0);
                __nv_bfloat16 g1 = __float2bfloat16(l1);
                hp[e] = (uint32_t)__bfloat16_as_ushort(h0) | ((uint32_t)__bfloat16_as_ushort(h1) << 16);
                lp[e] = (uint32_t)__bfloat16_as_ushort(g0) | ((uint32_t)__bfloat16_as_ushort(g1) << 16);
            }
            uint32_t off = tile_off(r, 64 + kb + q * 8);
            *(uint4*)(Ahi + off) = make_uint4(hp[0], hp[1], hp[2], hp[3]);
            *(uint4*)(Alo + off) = make_uint4(lp[0], lp[1], lp[2], lp[3]);
        }
    }
    TC_FENCE_BEFORE();
    FENCE_ASYNC();     // epilogue A-writes visible to async proxy
}

// ----------------------------------------------------------- main kernel ----
__global__ void __launch_bounds__(TPB, 1) nerf_main(
    const float* __restrict__ x, const float* __restrict__ dirg,
    const float* g1_0_b, const float* g1_1_b, const float* g1_2_b,
    const float* g1_3_b, const float* g1_4_b,
    const float* g2_0_b, const float* g2_1_b, const float* g2_2_b,
    const float* c_0_b,  const float* c_1_W,  const float* c_1_b,
    const float* sig_W,  const float* sig_b,
    float* __restrict__ out)
{
    extern __shared__ __align__(1024) char smem[];
    const uint32_t sb = smem_u32(smem);
    const int tid = threadIdx.x;
    const int w = tid >> 5, lane = tid & 31;
    char* Ahi = smem + AHI_OFF;
    char* Alo = smem + ALO_OFF;

    if (w == 0) { TC_ALLOC(sb + TMEMP_OFF, 512); TC_RELINQ(); }
    if (tid == 0) {
        #pragma unroll
        for (int b = 0; b < 4; ++b) {
            mbar_init(sb + MBAR_OFF + b * 8, 1);        // full[b]
            mbar_init(sb + MBAR_OFF + 32 + b * 8, 1);   // mma[b]
        }
        mbar_init(sb + MBAR_OFF + 64, 1);               // layer
        FENCE_ASYNC();
        // prologue: chunks 0,1,2 in flight during PE computation
        #pragma unroll
        for (int b = 0; b < 3; ++b) {
            mbar_expect_tx(sb + MBAR_OFF + b * 8, CH_BYTES);
            bulk_copy16k(sb + B_OFF + (uint32_t)b * CH_BYTES,
                         g_wscratch + (uint32_t)b * CH_BYTES,
                         sb + MBAR_OFF + b * 8);
        }
    }
    __syncthreads();
    uint32_t tmem;
    asm volatile("ld.shared.b32 %0, [%1];" : "=r"(tmem) : "r"(sb + TMEMP_OFF));

    const int row0 = blockIdx.x * MROWS;
    const int r = tid >> 2, p = tid & 3;

    if (tid < 128) a_store(Ahi, Alo, tid, 63, 0.f);

    {
        const float* xr = x + (size_t)(row0 + r) * 3;
        float x0 = xr[0], x1 = xr[1], x2 = xr[2];
        if (p == 0) {
            a_store(Ahi, Alo, r, 0, x0);
            a_store(Ahi, Alo, r, 1, x1);
            a_store(Ahi, Alo, r, 2, x2);
        }
        for (int l = p; l < 10; l += 4) {
            float f = (float)(1 << l);
            float s, c;
            sincosf(x0 * f, &s, &c); a_store(Ahi, Alo, r, 3 + 6 * l + 0, s); a_store(Ahi, Alo, r, 6 + 6 * l + 0, c);
            sincosf(x1 * f, &s, &c); a_store(Ahi, Alo, r, 3 + 6 * l + 1, s); a_store(Ahi, Alo, r, 6 + 6 * l + 1, c);
            sincosf(x2 * f, &s, &c); a_store(Ahi, Alo, r, 3 + 6 * l + 2, s); a_store(Ahi, Alo, r, 6 + 6 * l + 2, c);
        }
    }
    FENCE_ASYNC();

    Pipe pp;
    pp.gmma = 0; pp.gcopy = 3; pp.lpar = 0;
    #pragma unroll
    for (int b = 0; b < 4; ++b) { pp.pf[b] = 0; pp.pm[b] = 0; }

    run_layer(smem, sb, tmem,  4, 0, D1, g1_0_b, 1, 1, pp);
    run_layer(smem, sb, tmem, 16, 4, D1, g1_1_b, 1, 1, pp);
    run_layer(smem, sb, tmem, 16, 4, D1, g1_2_b, 1, 1, pp);
    run_layer(smem, sb, tmem, 16, 4, D1, g1_3_b, 1, 1, pp);
    run_layer(smem, sb, tmem, 16, 4, D1, g1_4_b, 0, 1, pp);
    run_layer(smem, sb, tmem, 20, 0, D1, g2_0_b, 1, 1, pp);

    // pe_d -> cols [24,63): safe, g2_0's layer barrier completed all its MMAs.
    {
        const float* dr = dirg + (size_t)(row0 + r) * 3;
        float d0 = dr[0], d1 = dr[1], d2 = dr[2];
        if (p == 0) {
            a_store(Ahi, Alo, r, 24, d0);
            a_store(Ahi, Alo, r, 25, d1);
            a_store(Ahi, Alo, r, 26, d2);
        }
        for (int l = p; l < 6; l += 4) {
            float f = (float)(1 << l);
            float s, c;
            sincosf(d0 * f, &s, &c); a_store(Ahi, Alo, r, 27 + 6 * l + 0, s); a_store(Ahi, Alo, r, 30 + 6 * l + 0, c);
            sincosf(d1 * f, &s, &c); a_store(Ahi, Alo, r, 27 + 6 * l + 1, s); a_store(Ahi, Alo, r, 30 + 6 * l + 1, c);
            sincosf(d2 * f, &s, &c); a_store(Ahi, Alo, r, 27 + 6 * l + 2, s); a_store(Ahi, Alo, r, 30 + 6 * l + 2, c);
        }
        FENCE_ASYNC();
    }

    run_layer(smem, sb, tmem, 16, 4, D1, g2_1_b, 1, 1, pp);
    run_layer(smem, sb, tmem, 16, 4, D2, g2_2_b, 0, 1, pp);   // features2 -> D2 (preact)
    run_layer(smem, sb, tmem, 20, 0, D1, c_0_b,  0, 0, pp);   // c_0 preact -> D1

    __syncthreads();
    TC_FENCE_AFTER();

    // stage head params into (now-idle) B region
    float* SWM = (float*)(smem + B_OFF);
    for (int i = tid; i < 256; i += TPB) {
        SWM[i]        = sig_W[i];
        SWM[256 + i]  = c_0_b[i];
        SWM[1536 + i] = g2_2_b[i];
    }
    for (int i = tid; i < 768; i += TPB) SWM[512 + i] = c_1_W[i];
    if (tid == 0) {
        SWM[1280] = sig_b[0];
        SWM[1281] = c_1_b[0]; SWM[1282] = c_1_b[1]; SWM[1283] = c_1_b[2];
    }
    __syncthreads();

    // heads: sigma = (D2 + g2_2_b) . sig_W + sig_b ; rgb = relu(D1 + c_0_b) @ c_1
    if (w < 4) {
        const int rr = w * 32 + lane;
        float sig = 0.f;
        for (int blk = 0; blk < 8; ++blk) {
            uint32_t rg[32];
            TC_LD_X32(rg, tmem + D2 + blk * 32);
            TC_WAIT_LD();
            #pragma unroll
            for (int i = 0; i < 32; ++i) {
                int k = blk * 32 + i;
                sig += (__uint_as_float(rg[i]) + SWM[1536 + k]) * SWM[k];
            }
        }
        float o0 = 0.f, o1 = 0.f, o2 = 0.f;
        for (int blk = 0; blk < 8; ++blk) {
            uint32_t rg[32];
            TC_LD_X32(rg, tmem + D1 + blk * 32);
            TC_WAIT_LD();
            #pragma unroll
            for (int i = 0; i < 32; ++i) {
                int k = blk * 32 + i;
                float f = fmaxf(__uint_as_float(rg[i]) + SWM[256 + k], 0.f);
                o0 += f * SWM[512 + 3 * k + 0];
                o1 += f * SWM[512 + 3 * k + 1];
                o2 += f * SWM[512 + 3 * k + 2];
            }
        }
        float4 o = make_float4(o0 + SWM[1281], o1 + SWM[1282], o2 + SWM[1283], sig + SWM[1280]);
        *(float4*)(out + (size_t)(row0 + rr) * 4) = o;
        TC_FENCE_BEFORE();
    }
    __syncthreads();
    if (w == 0) TC_DEALLOC(tmem, 512);
}

// ---------------------------------------------------------------- launch ----
extern "C" void kernel_launch(void* const* d_in, const int* in_sizes, int n_in,
                              void* d_out, int out_size)
{
    const float* x      = (const float*)d_in[0];
    const float* dirg   = (const float*)d_in[1];
    const float* g1_0_W = (const float*)d_in[2];  const float* g1_0_b = (const float*)d_in[3];
    const float* g1_1_W = (const float*)d_in[4];  const float* g1_1_b = (const float*)d_in[5];
    const float* g1_2_W = (const float*)d_in[6];  const float* g1_2_b = (const float*)d_in[7];
    const float* g1_3_W = (const float*)d_in[8];  const float* g1_3_b = (const float*)d_in[9];
    const float* g1_4_W = (const float*)d_in[10]; const float* g1_4_b = (const float*)d_in[11];
    const float* g2_0_W = (const float*)d_in[12]; const float* g2_0_b = (const float*)d_in[13];
    const float* g2_1_W = (const float*)d_in[14]; const float* g2_1_b = (const float*)d_in[15];
    const float* g2_2_W = (const float*)d_in[16]; const float* g2_2_b = (const float*)d_in[17];
    const float* c_0_W  = (const float*)d_in[18]; const float* c_0_b  = (const float*)d_in[19];
    const float* c_1_W  = (const float*)d_in[20]; const float* c_1_b  = (const float*)d_in[21];
    const float* sig_W  = (const float*)d_in[22]; const float* sig_b  = (const float*)d_in[23];
    float* out = (float*)d_out;

    const int N = in_sizes[0] / 3;           // 262144
    const int nblocks = N / MROWS;           // 2048

    dim3 pgrid(320, 9);
    nerf_prepass<<<pgrid, 256>>>(g1_0_W, g1_1_W, g1_2_W, g1_3_W, g1_4_W,
                                 g2_0_W, g2_1_W, g2_2_W, c_0_W);

    cudaFuncSetAttribute(nerf_main, cudaFuncAttributeMaxDynamicSharedMemorySize, SMEM_BYTES);
    nerf_main<<<nblocks, TPB, SMEM_BYTES>>>(
        x, dirg,
        g1_0_b, g1_1_b, g1_2_b, g1_3_b, g1_4_b,
        g2_0_b, g2_1_b, g2_2_b,
        c_0_b, c_1_W, c_1_b,
        sig_W, sig_b,
        out);
}

// round 13
// speedup vs baseline: 1.5436x; 1.1826x over previous
#include <cuda_runtime.h>
#include <cuda_bf16.h>
#include <cstdint>

// ============================================================================
// NeRF fused MLP on tcgen05 (bf16 2-term split, fp32 TMEM accumulate).
// R13: R12 warp-specialized pipeline + serialized-section cuts:
//   - per-layer bias staged to SMEM by warps 2-3 before the layer-drain wait
//   - packed bf16x2 epilogue conversions (cvt.rn.bf16x2.f32 + shift tricks)
//   - sigma head folded into g2_2's epilogue (register-resident features2),
//     partials via SMEM atomicAdd -> D2 eliminated, all layers accumulate D1
//   - rgb head parallelized across all 16 warps (col-split, B-region reduce)
//
// Pipeline (unchanged from R12): 140 flat 16KB SW64 chunks, 4 SMEM buffers,
// tid0 = MMA issuer (wait full -> 3 MMAs -> commit), tid32 = copy producer
// (wait drain -> cp.async.bulk), layer barrier via extra commit.
// ============================================================================

#if defined(__CUDA_ARCH_FEAT_SM103_ALL) || defined(__CUDA_ARCH_FEAT_SM100_ALL) || defined(__CUDA_ARCH_FEAT_SM101_ALL)
#define HAS_TC 1
#else
#define HAS_TC 0
#endif

#define TPB        512
#define MROWS      128
#define AHI_OFF    0
#define ALO_OFF    81920
#define B_OFF      163840            // 4 x 16KB buffers
#define TMEMP_OFF  229376
#define MBAR_OFF   229384            // full[4]@+0..31, mma[4]@+32..63, layer@+64
#define BIAS_OFF   229456            // 1KB: current layer bias
#define SIGW_OFF   230480            // 1KB: sig_W
#define SIGA_OFF   231504            // 512B: per-row sigma partials
#define SMEM_BYTES 232016
#define D1         0
#define CH_BYTES   16384u
#define NCH_TOTAL  140
// idesc kind::f16: dtype=F32(1<<4), a=BF16(1<<7), b=BF16(1<<10), N=256, M=128
#define IDESC      0x8400490u
#define WSCRATCH_BYTES (NCH_TOTAL * CH_BYTES)

__device__ __align__(128) unsigned char g_wscratch[WSCRATCH_BYTES];

static __device__ __forceinline__ uint32_t swz128(uint32_t b) { return b ^ ((b >> 3) & 0x70); }
static __device__ __forceinline__ uint32_t swz64(uint32_t b)  { return b ^ ((b >> 3) & 0x30); }
// A tile (SW128 blocked atoms, 128 rows x 320 K-cols)
static __device__ __forceinline__ uint32_t tile_off(int r, int k) {
    return (uint32_t)(((k >> 6) * 16 + (r >> 3)) * 1024)
         + swz128((uint32_t)(((r & 7) << 7) | ((k & 63) << 1)));
}
// B chunk frame (SW64, 256 rows x 32 cols bf16 = 64B rows)
static __device__ __forceinline__ uint32_t b_off64(int n, int c) {
    return (uint32_t)((n >> 3) * 512)
         + swz64((uint32_t)(((n & 7) << 6) | (c << 1)));
}
static __device__ __forceinline__ uint32_t smem_u32(const void* p) {
    uint32_t a;
    asm("{ .reg .u64 t; cvta.to.shared.u64 t, %1; cvt.u32.u64 %0, t; }" : "=r"(a) : "l"(p));
    return a;
}
static __device__ __forceinline__ uint64_t mkdesc128(uint32_t addr) {
    const uint64_t base = (uint64_t(2) << 61) | (uint64_t(1) << 46)
                        | (uint64_t(64) << 32) | (uint64_t(1) << 16);
    return base | ((uint64_t)(addr >> 4) & 0x3FFF);
}
static __device__ __forceinline__ uint64_t mkdesc64(uint32_t addr) {
    const uint64_t base = (uint64_t(4) << 61) | (uint64_t(1) << 46)
                        | (uint64_t(32) << 32) | (uint64_t(1) << 16);
    return base | ((uint64_t)(addr >> 4) & 0x3FFF);
}

static __device__ __forceinline__ void mma_ss(uint32_t d, uint64_t ad, uint64_t bd, uint32_t en) {
#if HAS_TC
    asm volatile(
        "{ .reg .pred p; setp.ne.u32 p, %5, 0;\n\t"
        "tcgen05.mma.cta_group::1.kind::f16 [%0], %1, %2, %3, {%4,%4,%4,%4}, p; }"
        :: "r"(d), "l"(ad), "l"(bd), "r"(IDESC), "r"(0u), "r"(en) : "memory");
#endif
}
static __device__ __forceinline__ void mbar_init(uint32_t a, uint32_t cnt) {
    asm volatile("mbarrier.init.shared.b64 [%0], %1;" :: "r"(a), "r"(cnt) : "memory");
}
static __device__ __forceinline__ void mbar_expect_tx(uint32_t a, uint32_t bytes) {
    asm volatile("mbarrier.arrive.expect_tx.shared.b64 _, [%0], %1;" :: "r"(a), "r"(bytes) : "memory");
}
static __device__ __forceinline__ void bulk_copy16k(uint32_t dst, const void* src, uint32_t mbar) {
    asm volatile(
        "cp.async.bulk.shared::cluster.global.mbarrier::complete_tx::bytes [%0], [%1], %2, [%3];"
        :: "r"(dst), "l"(src), "r"(CH_BYTES), "r"(mbar) : "memory");
}
static __device__ __forceinline__ void mbar_wait(uint32_t a, uint32_t parity) {
    uint32_t done;
    asm volatile(
        "{ .reg .pred p; mbarrier.try_wait.parity.acquire.cta.shared::cta.b64 p, [%1], %2;"
        " selp.b32 %0, 1, 0, p; }" : "=r"(done) : "r"(a), "r"(parity) : "memory");
    if (!done) {
        asm volatile(
            "{ .reg .pred P1;\n\t"
            "WL%=:\n\t"
            "mbarrier.try_wait.parity.acquire.cta.shared::cta.b64 P1, [%0], %1, 0x989680;\n\t"
            "@P1 bra WD%=;\n\t"
            "bra WL%=;\n\t"
            "WD%=:\n\t}" :: "r"(a), "r"(parity) : "memory");
    }
}

#if HAS_TC
#define TC_ALLOC(sa, n)   asm volatile("tcgen05.alloc.cta_group::1.sync.aligned.shared::cta.b32 [%0], %1;" :: "r"(sa), "r"(n) : "memory")
#define TC_RELINQ()       asm volatile("tcgen05.relinquish_alloc_permit.cta_group::1.sync.aligned;")
#define TC_DEALLOC(t, n)  asm volatile("tcgen05.dealloc.cta_group::1.sync.aligned.b32 %0, %1;" :: "r"(t), "r"(n))
#define TC_COMMIT(mb)     asm volatile("tcgen05.commit.cta_group::1.mbarrier::arrive::one.shared::cluster.b64 [%0];" :: "r"(mb) : "memory")
#define TC_FENCE_AFTER()  asm volatile("tcgen05.fence::after_thread_sync;" ::: "memory")
#define TC_FENCE_BEFORE() asm volatile("tcgen05.fence::before_thread_sync;" ::: "memory")
#define TC_WAIT_LD()      asm volatile("tcgen05.wait::ld.sync.aligned;" ::: "memory")
#define TC_LD_X32(r, ta) \
    asm volatile( \
        "tcgen05.ld.sync.aligned.32x32b.x32.b32 " \
        "{%0, %1, %2, %3, %4, %5, %6, %7, " \
        " %8, %9, %10, %11, %12, %13, %14, %15, " \
        " %16, %17, %18, %19, %20, %21, %22, %23, " \
        " %24, %25, %26, %27, %28, %29, %30, %31}, [%32];" \
        : "=r"((r)[0]),  "=r"((r)[1]),  "=r"((r)[2]),  "=r"((r)[3]), \
          "=r"((r)[4]),  "=r"((r)[5]),  "=r"((r)[6]),  "=r"((r)[7]), \
          "=r"((r)[8]),  "=r"((r)[9]),  "=r"((r)[10]), "=r"((r)[11]), \
          "=r"((r)[12]), "=r"((r)[13]), "=r"((r)[14]), "=r"((r)[15]), \
          "=r"((r)[16]), "=r"((r)[17]), "=r"((r)[18]), "=r"((r)[19]), \
          "=r"((r)[20]), "=r"((r)[21]), "=r"((r)[22]), "=r"((r)[23]), \
          "=r"((r)[24]), "=r"((r)[25]), "=r"((r)[26]), "=r"((r)[27]), \
          "=r"((r)[28]), "=r"((r)[29]), "=r"((r)[30]), "=r"((r)[31]) \
        : "r"(ta))
#else
#define TC_ALLOC(sa, n)   ((void)0)
#define TC_RELINQ()       ((void)0)
#define TC_DEALLOC(t, n)  ((void)0)
#define TC_COMMIT(mb)     ((void)0)
#define TC_FENCE_AFTER()  ((void)0)
#define TC_FENCE_BEFORE() ((void)0)
#define TC_WAIT_LD()      ((void)0)
#define TC_LD_X32(r, ta)  do { _Pragma("unroll") for (int _i = 0; _i < 32; ++_i) (r)[_i] = 0u; } while (0)
#endif
#define FENCE_ASYNC()     asm volatile("fence.proxy.async.shared::cta;" ::: "memory")

// packed split: hp = bf16x2(v0,v1) (lo=v0), lp = bf16x2 of residuals
static __device__ __forceinline__ void split2(float v0, float v1, uint32_t& hp, uint32_t& lp) {
    asm("cvt.rn.bf16x2.f32 %0, %1, %2;" : "=r"(hp) : "f"(v1), "f"(v0));
    float h0 = __uint_as_float(hp << 16);
    float h1 = __uint_as_float(hp & 0xffff0000u);
    float l0 = v0 - h0, l1 = v1 - h1;
    asm("cvt.rn.bf16x2.f32 %0, %1, %2;" : "=r"(lp) : "f"(l1), "f"(l0));
}

static __device__ __forceinline__ void a_store(char* Ahi, char* Alo, int r, int k, float v) {
    __nv_bfloat16 h = __float2bfloat16(v);
    float l = v - __bfloat162float(h);
    uint32_t o = tile_off(r, k);
    *(__nv_bfloat16*)(Ahi + o) = h;
    *(__nv_bfloat16*)(Alo + o) = __float2bfloat16(l);
}

// -------------------------------------------------------------- prepass -----
// Layer chunk bases (16KB chunks): L0@0(4), L1@4, L2@20, L3@36, L4@52,
// L5@68(20), L6@88, L7@104, L8@120(20). Total 140.
__global__ void nerf_prepass(
    const float* W0, const float* W1, const float* W2, const float* W3, const float* W4,
    const float* W5, const float* W6, const float* W7, const float* W8)
{
    int layer = blockIdx.y;
    int k = blockIdx.x;           // padded K index within layer
    int n = threadIdx.x;          // output neuron 0..255
    const float* W; int Kpad, kaoff, kalen, kblen; uint32_t cbase;
    switch (layer) {
        case 0: W = W0; Kpad = 64;  kaoff = 0;  kalen = 63;  kblen = 0;   cbase = 0;   break;
        case 1: W = W1; Kpad = 256; kaoff = 0;  kalen = 256; kblen = 0;   cbase = 4;   break;
        case 2: W = W2; Kpad = 256; kaoff = 0;  kalen = 256; kblen = 0;   cbase = 20;  break;
        case 3: W = W3; Kpad = 256; kaoff = 0;  kalen = 256; kblen = 0;   cbase = 36;  break;
        case 4: W = W4; Kpad = 256; kaoff = 0;  kalen = 256; kblen = 0;   cbase = 52;  break;
        case 5: W = W5; Kpad = 320; kaoff = 0;  kalen = 63;  kblen = 256; cbase = 68;  break;
        case 6: W = W6; Kpad = 256; kaoff = 0;  kalen = 256; kblen = 0;   cbase = 88;  break;
        case 7: W = W7; Kpad = 256; kaoff = 0;  kalen = 256; kblen = 0;   cbase = 104; break;
        default: W = W8; Kpad = 320; kaoff = 24; kalen = 39; kblen = 256; cbase = 120; break;
    }
    if (k >= Kpad) return;
    int row = -1;
    if (k >= kaoff && k < kaoff + kalen) row = k - kaoff;
    else if (kblen && k >= 64 && k < 64 + kblen) row = kalen + (k - 64);
    float v = (row >= 0) ? W[(size_t)row * 256 + n] : 0.f;

    uint32_t off = (cbase + (uint32_t)(k >> 4)) * CH_BYTES;
    int local = k & 15;
    __nv_bfloat16 h = __float2bfloat16(v);
    float l = v - __bfloat162float(h);
    *(__nv_bfloat16*)(g_wscratch + off + b_off64(n, local))      = h;
    *(__nv_bfloat16*)(g_wscratch + off + b_off64(n, 16 + local)) = __float2bfloat16(l);
}

// ------------------------------------------------------------- run_layer ----
struct Pipe { int gmma, gcopy, lpar; int pf[4], pm[4]; };

static __device__ __noinline__ void run_layer(
    char* smem, uint32_t sb, uint32_t tmem,
    int nch, int a_step0,
    const float* __restrict__ bias, int relu, int do_epi, int do_sig, Pipe& pp)
{
    const int tid = threadIdx.x;
    const int w = tid >> 5;
    __syncthreads();   // prev epilogue / PE A-writes done; bias_s free

    // stage this layer's bias into SMEM (hidden behind the MMA drain)
    if (tid >= 64 && tid < 128)
        ((float4*)(smem + BIAS_OFF))[tid - 64] = __ldg((const float4*)bias + (tid - 64));

    if (tid == 0) {
        // ---- MMA issuer: no free-waits, no copies; paced by tcgen05 queue.
        const uint64_t adh = mkdesc128(sb + AHI_OFF);
        const uint64_t adl = mkdesc128(sb + ALO_OFF);
        uint64_t bds[4];
        #pragma unroll
        for (int b = 0; b < 4; ++b) bds[b] = mkdesc64(sb + B_OFF + (uint32_t)b * CH_BYTES);
        for (int i = 0; i < nch; ++i) {
            const int g = pp.gmma++;
            const int buf = g & 3;
            mbar_wait(sb + MBAR_OFF + buf * 8, (uint32_t)pp.pf[buf]);
            pp.pf[buf] ^= 1;
            const int s = a_step0 + i;
            const uint64_t aoff = (uint64_t)((s >> 2) * 1024 + (s & 3) * 2);
            mma_ss(tmem + D1, adh + aoff, bds[buf],     i > 0);  // Ahi*Bhi
            mma_ss(tmem + D1, adh + aoff, bds[buf] + 2, 1u);     // Ahi*Blo
            mma_ss(tmem + D1, adl + aoff, bds[buf],     1u);     // Alo*Bhi
            TC_COMMIT(sb + MBAR_OFF + 32 + buf * 8);
        }
        TC_COMMIT(sb + MBAR_OFF + 64);   // layer-done barrier
    } else if (tid == 32) {
        // ---- Copy producer: frees buffers + streams chunks, fully overlapped.
        for (int i = 0; i < nch; ++i) {
            const int t = pp.gcopy;
            if (t >= NCH_TOTAL) break;
            const int cb = t & 3;
            if (t >= 4) {   // chunk t-4 used this buffer; wait its MMAs drained
                mbar_wait(sb + MBAR_OFF + 32 + cb * 8, (uint32_t)pp.pm[cb]);
                pp.pm[cb] ^= 1;
            }
            mbar_expect_tx(sb + MBAR_OFF + cb * 8, CH_BYTES);
            bulk_copy16k(sb + B_OFF + (uint32_t)cb * CH_BYTES,
                         g_wscratch + (uint32_t)t * CH_BYTES,
                         sb + MBAR_OFF + cb * 8);
            pp.gcopy = t + 1;
        }
    }
    // all threads: wait layer completion
    mbar_wait(sb + MBAR_OFF + 64, (uint32_t)pp.lpar);
    pp.lpar ^= 1;
    TC_FENCE_AFTER();
    if (!do_epi) return;
    __syncthreads();   // bias_s stores visible to all epilogue readers

    const int lane = tid & 31;
    const int r  = (w & 3) * 32 + lane;
    const int c0 = (w >> 2) * 64;
    char* Ahi = smem + AHI_OFF;
    char* Alo = smem + ALO_OFF;
    const float* bias_s = (const float*)(smem + BIAS_OFF);
    const float* sw = (const float*)(smem + SIGW_OFF);
    float sg = 0.f;

    #pragma unroll
    for (int h = 0; h < 2; ++h) {
        uint32_t rg[32];
        TC_LD_X32(rg, tmem + D1 + c0 + h * 32);
        TC_WAIT_LD();
        const int kb = c0 + h * 32;
        #pragma unroll
        for (int q = 0; q < 4; ++q) {
            float4 b0 = *(const float4*)(bias_s + kb + q * 8);
            float4 b1 = *(const float4*)(bias_s + kb + q * 8 + 4);
            float v[8];
            v[0] = __uint_as_float(rg[q * 8 + 0]) + b0.x;
            v[1] = __uint_as_float(rg[q * 8 + 1]) + b0.y;
            v[2] = __uint_as_float(rg[q * 8 + 2]) + b0.z;
            v[3] = __uint_as_float(rg[q * 8 + 3]) + b0.w;
            v[4] = __uint_as_float(rg[q * 8 + 4]) + b1.x;
            v[5] = __uint_as_float(rg[q * 8 + 5]) + b1.y;
            v[6] = __uint_as_float(rg[q * 8 + 6]) + b1.z;
            v[7] = __uint_as_float(rg[q * 8 + 7]) + b1.w;
            if (relu) {
                #pragma unroll
                for (int e = 0; e < 8; ++e) v[e] = fmaxf(v[e], 0.f);
            }
            if (do_sig) {
                #pragma unroll
                for (int e = 0; e < 8; ++e) sg += v[e] * sw[kb + q * 8 + e];
            }
            uint32_t hp[4], lp[4];
            #pragma unroll
            for (int e = 0; e < 4; ++e) split2(v[2 * e], v[2 * e + 1], hp[e], lp[e]);
            uint32_t off = tile_off(r, 64 + kb + q * 8);
            *(uint4*)(Ahi + off) = make_uint4(hp[0], hp[1], hp[2], hp[3]);
            *(uint4*)(Alo + off) = make_uint4(lp[0], lp[1], lp[2], lp[3]);
        }
    }
    if (do_sig) atomicAdd((float*)(smem + SIGA_OFF) + r, sg);
    TC_FENCE_BEFORE();
    FENCE_ASYNC();     // epilogue A-writes visible to async proxy
}

// ----------------------------------------------------------- main kernel ----
__global__ void __launch_bounds__(TPB, 1) nerf_main(
    const float* __restrict__ x, const float* __restrict__ dirg,
    const float* g1_0_b, const float* g1_1_b, const float* g1_2_b,
    const float* g1_3_b, const float* g1_4_b,
    const float* g2_0_b, const float* g2_1_b, const float* g2_2_b,
    const float* c_0_b,  const float* c_1_W,  const float* c_1_b,
    const float* sig_W,  const float* sig_b,
    float* __restrict__ out)
{
    extern __shared__ __align__(1024) char smem[];
    const uint32_t sb = smem_u32(smem);
    const int tid = threadIdx.x;
    const int w = tid >> 5, lane = tid & 31;
    char* Ahi = smem + AHI_OFF;
    char* Alo = smem + ALO_OFF;

    if (w == 0) { TC_ALLOC(sb + TMEMP_OFF, 512); TC_RELINQ(); }
    if (tid == 0) {
        #pragma unroll
        for (int b = 0; b < 4; ++b) {
            mbar_init(sb + MBAR_OFF + b * 8, 1);        // full[b]
            mbar_init(sb + MBAR_OFF + 32 + b * 8, 1);   // mma[b]
        }
        mbar_init(sb + MBAR_OFF + 64, 1);               // layer
        FENCE_ASYNC();
        // prologue: chunks 0,1,2 in flight during PE computation
        #pragma unroll
        for (int b = 0; b < 3; ++b) {
            mbar_expect_tx(sb + MBAR_OFF + b * 8, CH_BYTES);
            bulk_copy16k(sb + B_OFF + (uint32_t)b * CH_BYTES,
                         g_wscratch + (uint32_t)b * CH_BYTES,
                         sb + MBAR_OFF + b * 8);
        }
    }
    // stage sig_W + zero sigma partials (once)
    if (tid < 64) ((float4*)(smem + SIGW_OFF))[tid] = __ldg((const float4*)sig_W + tid);
    if (tid < 128) ((float*)(smem + SIGA_OFF))[tid] = 0.f;
    __syncthreads();
    uint32_t tmem;
    asm volatile("ld.shared.b32 %0, [%1];" : "=r"(tmem) : "r"(sb + TMEMP_OFF));

    const int row0 = blockIdx.x * MROWS;
    const int r = tid >> 2, p = tid & 3;

    if (tid < 128) a_store(Ahi, Alo, tid, 63, 0.f);

    {
        const float* xr = x + (size_t)(row0 + r) * 3;
        float x0 = xr[0], x1 = xr[1], x2 = xr[2];
        if (p == 0) {
            a_store(Ahi, Alo, r, 0, x0);
            a_store(Ahi, Alo, r, 1, x1);
            a_store(Ahi, Alo, r, 2, x2);
        }
        for (int l = p; l < 10; l += 4) {
            float f = (float)(1 << l);
            float s, c;
            sincosf(x0 * f, &s, &c); a_store(Ahi, Alo, r, 3 + 6 * l + 0, s); a_store(Ahi, Alo, r, 6 + 6 * l + 0, c);
            sincosf(x1 * f, &s, &c); a_store(Ahi, Alo, r, 3 + 6 * l + 1, s); a_store(Ahi, Alo, r, 6 + 6 * l + 1, c);
            sincosf(x2 * f, &s, &c); a_store(Ahi, Alo, r, 3 + 6 * l + 2, s); a_store(Ahi, Alo, r, 6 + 6 * l + 2, c);
        }
    }
    FENCE_ASYNC();

    Pipe pp;
    pp.gmma = 0; pp.gcopy = 3; pp.lpar = 0;
    #pragma unroll
    for (int b = 0; b < 4; ++b) { pp.pf[b] = 0; pp.pm[b] = 0; }

    run_layer(smem, sb, tmem,  4, 0, g1_0_b, 1, 1, 0, pp);
    run_layer(smem, sb, tmem, 16, 4, g1_1_b, 1, 1, 0, pp);
    run_layer(smem, sb, tmem, 16, 4, g1_2_b, 1, 1, 0, pp);
    run_layer(smem, sb, tmem, 16, 4, g1_3_b, 1, 1, 0, pp);
    run_layer(smem, sb, tmem, 16, 4, g1_4_b, 0, 1, 0, pp);
    run_layer(smem, sb, tmem, 20, 0, g2_0_b, 1, 1, 0, pp);

    // pe_d -> cols [24,63): safe, g2_0's layer barrier completed all its MMAs.
    {
        const float* dr = dirg + (size_t)(row0 + r) * 3;
        float d0 = dr[0], d1 = dr[1], d2 = dr[2];
        if (p == 0) {
            a_store(Ahi, Alo, r, 24, d0);
            a_store(Ahi, Alo, r, 25, d1);
            a_store(Ahi, Alo, r, 26, d2);
        }
        for (int l = p; l < 6; l += 4) {
            float f = (float)(1 << l);
            float s, c;
            sincosf(d0 * f, &s, &c); a_store(Ahi, Alo, r, 27 + 6 * l + 0, s); a_store(Ahi, Alo, r, 30 + 6 * l + 0, c);
            sincosf(d1 * f, &s, &c); a_store(Ahi, Alo, r, 27 + 6 * l + 1, s); a_store(Ahi, Alo, r, 30 + 6 * l + 1, c);
            sincosf(d2 * f, &s, &c); a_store(Ahi, Alo, r, 27 + 6 * l + 2, s); a_store(Ahi, Alo, r, 30 + 6 * l + 2, c);
        }
        FENCE_ASYNC();
    }

    run_layer(smem, sb, tmem, 16, 4, g2_1_b, 1, 1, 0, pp);
    run_layer(smem, sb, tmem, 16, 4, g2_2_b, 0, 1, 1, pp);   // feat2 + sigma fold
    run_layer(smem, sb, tmem, 20, 0, c_0_b,  0, 0, 0, pp);   // c_0 preact in D1; bias_s = c_0_b

    __syncthreads();
    TC_FENCE_AFTER();

    // stage rgb head params into (now-idle) B region
    float* SWM = (float*)(smem + B_OFF);
    for (int i = tid; i < 768; i += TPB) SWM[i] = __ldg(c_1_W + i);
    if (tid == 0) {
        SWM[768] = sig_b[0];
        SWM[769] = c_1_b[0]; SWM[770] = c_1_b[1]; SWM[771] = c_1_b[2];
    }
    float* PART = (float*)(smem + B_OFF + 8192);
    __syncthreads();

    // rgb head, all 16 warps: col group cb = w>>2, rows (w&3)*32+lane
    {
        const int cb = w >> 2;
        const int rr = (w & 3) * 32 + lane;
        const float* bias_s = (const float*)(smem + BIAS_OFF);   // = c_0_b (L8 staging)
        float o0 = 0.f, o1 = 0.f, o2 = 0.f;
        #pragma unroll
        for (int blk = 0; blk < 2; ++blk) {
            uint32_t rg[32];
            TC_LD_X32(rg, tmem + D1 + cb * 64 + blk * 32);
            TC_WAIT_LD();
            #pragma unroll
            for (int i = 0; i < 32; ++i) {
                int k = cb * 64 + blk * 32 + i;
                float f = fmaxf(__uint_as_float(rg[i]) + bias_s[k], 0.f);
                o0 += f * SWM[3 * k + 0];
                o1 += f * SWM[3 * k + 1];
                o2 += f * SWM[3 * k + 2];
            }
        }
        float* pd = PART + (cb * 128 + rr) * 4;
        pd[0] = o0; pd[1] = o1; pd[2] = o2;
    }
    __syncthreads();
    if (w < 4) {
        const int rr = w * 32 + lane;
        float o0 = 0.f, o1 = 0.f, o2 = 0.f;
        #pragma unroll
        for (int g = 0; g < 4; ++g) {
            const float* pd = PART + (g * 128 + rr) * 4;
            o0 += pd[0]; o1 += pd[1]; o2 += pd[2];
        }
        float sig = ((const float*)(smem + SIGA_OFF))[rr] + SWM[768];
        float4 o = make_float4(o0 + SWM[769], o1 + SWM[770], o2 + SWM[771], sig);
        *(float4*)(out + (size_t)(row0 + rr) * 4) = o;
        TC_FENCE_BEFORE();
    }
    __syncthreads();
    if (w == 0) TC_DEALLOC(tmem, 512);
}

// ---------------------------------------------------------------- launch ----
extern "C" void kernel_launch(void* const* d_in, const int* in_sizes, int n_in,
                              void* d_out, int out_size)
{
    const float* x      = (const float*)d_in[0];
    const float* dirg   = (const float*)d_in[1];
    const float* g1_0_W = (const float*)d_in[2];  const float* g1_0_b = (const float*)d_in[3];
    const float* g1_1_W = (const float*)d_in[4];  const float* g1_1_b = (const float*)d_in[5];
    const float* g1_2_W = (const float*)d_in[6];  const float* g1_2_b = (const float*)d_in[7];
    const float* g1_3_W = (const float*)d_in[8];  const float* g1_3_b = (const float*)d_in[9];
    const float* g1_4_W = (const float*)d_in[10]; const float* g1_4_b = (const float*)d_in[11];
    const float* g2_0_W = (const float*)d_in[12]; const float* g2_0_b = (const float*)d_in[13];
    const float* g2_1_W = (const float*)d_in[14]; const float* g2_1_b = (const float*)d_in[15];
    const float* g2_2_W = (const float*)d_in[16]; const float* g2_2_b = (const float*)d_in[17];
    const float* c_0_W  = (const float*)d_in[18]; const float* c_0_b  = (const float*)d_in[19];
    const float* c_1_W  = (const float*)d_in[20]; const float* c_1_b  = (const float*)d_in[21];
    const float* sig_W  = (const float*)d_in[22]; const float* sig_b  = (const float*)d_in[23];
    float* out = (float*)d_out;

    const int N = in_sizes[0] / 3;           // 262144
    const int nblocks = N / MROWS;           // 2048

    dim3 pgrid(320, 9);
    nerf_prepass<<<pgrid, 256>>>(g1_0_W, g1_1_W, g1_2_W, g1_3_W, g1_4_W,
                                 g2_0_W, g2_1_W, g2_2_W, c_0_W);

    cudaFuncSetAttribute(nerf_main, cudaFuncAttributeMaxDynamicSharedMemorySize, SMEM_BYTES);
    nerf_main<<<nblocks, TPB, SMEM_BYTES>>>(
        x, dirg,
        g1_0_b, g1_1_b, g1_2_b, g1_3_b, g1_4_b,
        g2_0_b, g2_1_b, g2_2_b,
        c_0_b, c_1_W, c_1_b,
        sig_W, sig_b,
        out);
}